// round 5
// baseline (speedup 1.0000x reference)
#include <cuda_runtime.h>
#include <cuda_fp16.h>
#include <math.h>

// Problem constants (fixed shapes)
#define Bb 64
#define Vv 100000
#define Ff 200000
#define Ee (6 * Ff)          // 1,200,000 adjacency entries
#define VT_STRIDE 192        // per-vertex halves: 3 comps * 64 batches

// -------- device scratch (static; no allocations allowed) --------
__device__ int    g_deg[Vv];
__device__ int    g_rowptr[Vv + 1];
__device__ int    g_cursor[Vv];
__device__ int    g_adj[Ee];
__device__ __align__(16) __half g_vT[(size_t)Vv * VT_STRIDE];   // 38.4 MB, layout [v][c][b] fp16
__device__ int    g_blocksums[256];
__device__ float  g_accum;
__device__ int    g_done;
__device__ int    g_faces64;   // 1 if faces buffer is int64, 0 if int32

// -------- 1) init degrees + detect faces dtype + clear accum/ticket --------
// int64 values < 2^31 -> every odd 32-bit word is 0. int32 random ids -> P(all 64 odd words==0)~0.
__global__ void k_init(const int* __restrict__ faces_w) {
    int idx = blockIdx.x * blockDim.x + threadIdx.x;
    if (idx < Vv) g_deg[idx] = 0;
    if (idx == 0) {
        int nz = 0;
        #pragma unroll
        for (int t = 0; t < 64; t++) nz |= faces_w[2 * t + 1];
        g_faces64 = (nz == 0) ? 1 : 0;
        g_accum = 0.0f;
        g_done  = 0;
    }
}

__device__ __forceinline__ void load_face(const int* __restrict__ fw, int f, int w64,
                                          int& i, int& j, int& k) {
    if (w64) {
        i = fw[6 * f + 0];
        j = fw[6 * f + 2];
        k = fw[6 * f + 4];
    } else {
        i = fw[3 * f + 0];
        j = fw[3 * f + 1];
        k = fw[3 * f + 2];
    }
}

// -------- 2) degree count --------
__global__ void k_count(const int* __restrict__ faces_w) {
    int f = blockIdx.x * blockDim.x + threadIdx.x;
    if (f >= Ff) return;
    int w64 = g_faces64;
    int i, j, k;
    load_face(faces_w, f, w64, i, j, k);
    atomicAdd(&g_deg[i], 2);
    atomicAdd(&g_deg[j], 2);
    atomicAdd(&g_deg[k], 2);
}

// -------- 3) scan, level 1 (512-wide blocks, warp shuffles) --------
#define SCAN_BS 512
#define SCAN_NB ((Vv + SCAN_BS - 1) / SCAN_BS)   // 196

__global__ void k_scan1() {
    __shared__ int wsum[16];
    int tid = threadIdx.x, lane = tid & 31, w = tid >> 5;
    int gid = blockIdx.x * SCAN_BS + tid;
    int val = (gid < Vv) ? g_deg[gid] : 0;
    int x = val;
    #pragma unroll
    for (int off = 1; off < 32; off <<= 1) {
        int y = __shfl_up_sync(0xFFFFFFFFu, x, off);
        if (lane >= off) x += y;
    }
    if (lane == 31) wsum[w] = x;
    __syncthreads();
    if (w == 0) {
        int s = (lane < 16) ? wsum[lane] : 0;
        #pragma unroll
        for (int off = 1; off < 16; off <<= 1) {
            int y = __shfl_up_sync(0xFFFFFFFFu, s, off);
            if (lane >= off) s += y;
        }
        if (lane < 16) wsum[lane] = s;
    }
    __syncthreads();
    int base = (w > 0) ? wsum[w - 1] : 0;
    int incl = base + x;
    if (gid < Vv) g_rowptr[gid] = incl - val;        // exclusive within block
    if (tid == SCAN_BS - 1) g_blocksums[blockIdx.x] = incl;
}

// -------- 3b) scan finalize: each block redundantly scans the 196 block sums,
//              then applies offsets and writes rowptr + cursor --------
__global__ void k_scan3() {
    __shared__ int spre[256];   // exclusive prefix of blocksums
    __shared__ int wsum[8];
    int tid = threadIdx.x, lane = tid & 31, w = tid >> 5;   // 256 threads
    int val = (tid < SCAN_NB) ? g_blocksums[tid] : 0;
    int x = val;
    #pragma unroll
    for (int off = 1; off < 32; off <<= 1) {
        int y = __shfl_up_sync(0xFFFFFFFFu, x, off);
        if (lane >= off) x += y;
    }
    if (lane == 31) wsum[w] = x;
    __syncthreads();
    if (w == 0) {
        int s = (lane < 8) ? wsum[lane] : 0;
        #pragma unroll
        for (int off = 1; off < 8; off <<= 1) {
            int y = __shfl_up_sync(0xFFFFFFFFu, s, off);
            if (lane >= off) s += y;
        }
        if (lane < 8) wsum[lane] = s;
    }
    __syncthreads();
    int base = (w > 0) ? wsum[w - 1] : 0;
    spre[tid] = base + x - val;                       // exclusive blocksum prefix
    __syncthreads();

    int gid = blockIdx.x * blockDim.x + tid;
    if (gid < Vv) {
        int r = g_rowptr[gid] + spre[gid / SCAN_BS];
        g_rowptr[gid] = r;
        g_cursor[gid] = r;
    }
    if (gid == 0) g_rowptr[Vv] = Ee;
}

// -------- 4) CSR fill --------
__global__ void k_fill(const int* __restrict__ faces_w) {
    int f = blockIdx.x * blockDim.x + threadIdx.x;
    if (f >= Ff) return;
    int w64 = g_faces64;
    int i, j, k;
    load_face(faces_w, f, w64, i, j, k);
    int p;
    p = atomicAdd(&g_cursor[i], 2); g_adj[p] = j; g_adj[p + 1] = k;
    p = atomicAdd(&g_cursor[j], 2); g_adj[p] = i; g_adj[p + 1] = k;
    p = atomicAdd(&g_cursor[k], 2); g_adj[p] = j; g_adj[p + 1] = i;
}

// -------- 5) transpose verts [B][V][3] f32 -> vT [V][3][B] fp16 --------
#define TP_VT 32
__global__ void k_transpose(const float* __restrict__ verts) {
    __shared__ float sh[TP_VT * 3 * 65];   // [rem=v*3+c][b], padded 65 to kill bank conflicts
    int t = threadIdx.x;                   // 256 threads
    int v0 = blockIdx.x * TP_VT;           // V = 100000 = 32 * 3125, exact

    #pragma unroll
    for (int it = 0; it < 24; it++) {
        int l = it * 256 + t;
        int b = l / 96;
        int rem = l - b * 96;
        float val = verts[(size_t)b * (Vv * 3) + (size_t)v0 * 3 + rem];
        sh[rem * 65 + b] = val;
    }
    __syncthreads();

    __half2* out = (__half2*)(g_vT + (size_t)v0 * VT_STRIDE);
    #pragma unroll
    for (int it = 0; it < 12; it++) {
        int o = it * 256 + t;              // half2 index within tile
        int v = o / 96;
        int r = o - v * 96;
        int c = r >> 5;                    // component
        int bp = r & 31;                   // batch pair
        float f0 = sh[(v * 3 + c) * 65 + 2 * bp];
        float f1 = sh[(v * 3 + c) * 65 + 2 * bp + 1];
        out[o] = __floats2half2_rn(f0, f1);
    }
}

// -------- 6) gather + norm + reduce + fused finalize --------
// One warp per vertex, lane owns 2 batches; 1-ahead software pipeline.
#define GATHER_WARPS 8
__global__ void __launch_bounds__(256) k_gather(float* __restrict__ out) {
    int lane = threadIdx.x & 31;
    int wid  = threadIdx.x >> 5;
    int v    = blockIdx.x * GATHER_WARPS + wid;

    float nsum = 0.0f;
    if (v < Vv) {
        const __half2* vt2 = (const __half2*)g_vT;   // per-vertex stride 96 half2
        int s = g_rowptr[v];
        int e = g_rowptr[v + 1];

        float ax0 = 0.f, ax1 = 0.f, ay0 = 0.f, ay1 = 0.f, az0 = 0.f, az1 = 0.f;
        if (s < e) {
            int u = __ldg(&g_adj[s]);
            const __half2* p = vt2 + (size_t)u * 96;
            __half2 hx = __ldg(&p[lane]);
            __half2 hy = __ldg(&p[32 + lane]);
            __half2 hz = __ldg(&p[64 + lane]);
            for (int t = s + 1; t < e; t++) {
                int u2 = __ldg(&g_adj[t]);                 // prefetch next neighbor
                const __half2* p2 = vt2 + (size_t)u2 * 96;
                __half2 nx = __ldg(&p2[lane]);
                __half2 ny = __ldg(&p2[32 + lane]);
                __half2 nz = __ldg(&p2[64 + lane]);
                float2 fx = __half22float2(hx);
                float2 fy = __half22float2(hy);
                float2 fz = __half22float2(hz);
                ax0 += fx.x; ax1 += fx.y;
                ay0 += fy.x; ay1 += fy.y;
                az0 += fz.x; az1 += fz.y;
                hx = nx; hy = ny; hz = nz;
            }
            float2 fx = __half22float2(hx);
            float2 fy = __half22float2(hy);
            float2 fz = __half22float2(hz);
            ax0 += fx.x; ax1 += fx.y;
            ay0 += fy.x; ay1 += fy.y;
            az0 += fz.x; az1 += fz.y;
        }

        const __half2* pc = vt2 + (size_t)v * 96;
        float2 cx = __half22float2(pc[lane]);
        float2 cy = __half22float2(pc[32 + lane]);
        float2 cz = __half22float2(pc[64 + lane]);
        float invd = 1.0f / fmaxf((float)(e - s), 1.0f);

        float dx0 = cx.x - ax0 * invd, dy0 = cy.x - ay0 * invd, dz0 = cz.x - az0 * invd;
        float dx1 = cx.y - ax1 * invd, dy1 = cy.y - ay1 * invd, dz1 = cz.y - az1 * invd;
        nsum = sqrtf(dx0 * dx0 + dy0 * dy0 + dz0 * dz0)
             + sqrtf(dx1 * dx1 + dy1 * dy1 + dz1 * dz1);
    }

    // warp reduce
    #pragma unroll
    for (int off = 16; off > 0; off >>= 1)
        nsum += __shfl_xor_sync(0xFFFFFFFFu, nsum, off);

    __shared__ float warpsum[GATHER_WARPS];
    if (lane == 0) warpsum[wid] = nsum;
    __syncthreads();
    if (wid == 0) {
        float bsum = (lane < GATHER_WARPS) ? warpsum[lane] : 0.0f;
        #pragma unroll
        for (int off = 4; off > 0; off >>= 1)
            bsum += __shfl_xor_sync(0xFFFFFFFFu, bsum, off);
        if (lane == 0) {
            atomicAdd(&g_accum, bsum);
            __threadfence();
            int ticket = atomicAdd(&g_done, 1);
            if (ticket == (int)gridDim.x - 1) {
                float total = *(volatile float*)&g_accum;
                out[0] = total * (1.0f / ((float)Bb * (float)Vv));
            }
        }
    }
}

extern "C" void kernel_launch(void* const* d_in, const int* in_sizes, int n_in,
                              void* d_out, int out_size) {
    const float* verts   = (const float*)d_in[0];   // (64, 100000, 3) f32
    const int*   faces_w = (const int*)d_in[1];     // (200000, 3) int32 OR int64 (detected)
    float* out = (float*)d_out;

    (void)in_sizes; (void)n_in; (void)out_size;

    k_init<<<(Vv + 255) / 256, 256>>>(faces_w);
    k_count<<<(Ff + 255) / 256, 256>>>(faces_w);
    k_scan1<<<SCAN_NB, SCAN_BS>>>();
    k_scan3<<<(Vv + 255) / 256, 256>>>();
    k_fill<<<(Ff + 255) / 256, 256>>>(faces_w);
    k_transpose<<<Vv / TP_VT, 256>>>(verts);
    k_gather<<<(Vv + GATHER_WARPS - 1) / GATHER_WARPS, 256>>>(out);
}

// round 6
// speedup vs baseline: 1.4219x; 1.4219x over previous
#include <cuda_runtime.h>
#include <cuda_fp16.h>
#include <math.h>

// Problem constants (fixed shapes)
#define Bb 64
#define Vv 100000
#define Ff 200000
#define Ee (6 * Ff)          // 1,200,000 adjacency entries
#define VT_STRIDE 192        // per-vertex halves: 3 comps * 64 batches

// -------- device scratch (static; no allocations allowed) --------
__device__ int    g_deg[Vv];
__device__ int    g_rowptr[Vv + 1];
__device__ int    g_cursor[Vv];
__device__ int    g_adj[Ee];
__device__ __align__(16) __half g_vT[(size_t)Vv * VT_STRIDE];   // 38.4 MB, layout [v][c][b] fp16
__device__ int    g_blocksums[256];
__device__ float  g_accum;
__device__ int    g_done;
__device__ int    g_faces64;   // 1 if faces buffer is int64, 0 if int32

// -------- 1) init degrees + detect faces dtype + clear accum/ticket --------
// int64 values < 2^31 -> every odd 32-bit word is 0. int32 random ids -> P(all 64 odd words==0)~0.
__global__ void k_init(const int* __restrict__ faces_w) {
    int idx = blockIdx.x * blockDim.x + threadIdx.x;
    if (idx < Vv) g_deg[idx] = 0;
    if (idx == 0) {
        int nz = 0;
        #pragma unroll
        for (int t = 0; t < 64; t++) nz |= faces_w[2 * t + 1];
        g_faces64 = (nz == 0) ? 1 : 0;
        g_accum = 0.0f;
        g_done  = 0;
    }
}

__device__ __forceinline__ void load_face(const int* __restrict__ fw, int f, int w64,
                                          int& i, int& j, int& k) {
    if (w64) {
        i = fw[6 * f + 0];
        j = fw[6 * f + 2];
        k = fw[6 * f + 4];
    } else {
        i = fw[3 * f + 0];
        j = fw[3 * f + 1];
        k = fw[3 * f + 2];
    }
}

// -------- 2) degree count --------
__global__ void k_count(const int* __restrict__ faces_w) {
    int f = blockIdx.x * blockDim.x + threadIdx.x;
    if (f >= Ff) return;
    int w64 = g_faces64;
    int i, j, k;
    load_face(faces_w, f, w64, i, j, k);
    atomicAdd(&g_deg[i], 2);
    atomicAdd(&g_deg[j], 2);
    atomicAdd(&g_deg[k], 2);
}

// -------- 3) scan, level 1 (512-wide blocks, warp shuffles) --------
#define SCAN_BS 512
#define SCAN_NB ((Vv + SCAN_BS - 1) / SCAN_BS)   // 196

__global__ void k_scan1() {
    __shared__ int wsum[16];
    int tid = threadIdx.x, lane = tid & 31, w = tid >> 5;
    int gid = blockIdx.x * SCAN_BS + tid;
    int val = (gid < Vv) ? g_deg[gid] : 0;
    int x = val;
    #pragma unroll
    for (int off = 1; off < 32; off <<= 1) {
        int y = __shfl_up_sync(0xFFFFFFFFu, x, off);
        if (lane >= off) x += y;
    }
    if (lane == 31) wsum[w] = x;
    __syncthreads();
    if (w == 0) {
        int s = (lane < 16) ? wsum[lane] : 0;
        #pragma unroll
        for (int off = 1; off < 16; off <<= 1) {
            int y = __shfl_up_sync(0xFFFFFFFFu, s, off);
            if (lane >= off) s += y;
        }
        if (lane < 16) wsum[lane] = s;
    }
    __syncthreads();
    int base = (w > 0) ? wsum[w - 1] : 0;
    int incl = base + x;
    if (gid < Vv) g_rowptr[gid] = incl - val;        // exclusive within block
    if (tid == SCAN_BS - 1) g_blocksums[blockIdx.x] = incl;
}

// -------- 3b) scan finalize: each block redundantly scans the 196 block sums,
//              then applies offsets and writes rowptr + cursor --------
__global__ void k_scan3() {
    __shared__ int spre[256];   // exclusive prefix of blocksums
    __shared__ int wsum[8];
    int tid = threadIdx.x, lane = tid & 31, w = tid >> 5;   // 256 threads
    int val = (tid < SCAN_NB) ? g_blocksums[tid] : 0;
    int x = val;
    #pragma unroll
    for (int off = 1; off < 32; off <<= 1) {
        int y = __shfl_up_sync(0xFFFFFFFFu, x, off);
        if (lane >= off) x += y;
    }
    if (lane == 31) wsum[w] = x;
    __syncthreads();
    if (w == 0) {
        int s = (lane < 8) ? wsum[lane] : 0;
        #pragma unroll
        for (int off = 1; off < 8; off <<= 1) {
            int y = __shfl_up_sync(0xFFFFFFFFu, s, off);
            if (lane >= off) s += y;
        }
        if (lane < 8) wsum[lane] = s;
    }
    __syncthreads();
    int base = (w > 0) ? wsum[w - 1] : 0;
    spre[tid] = base + x - val;                       // exclusive blocksum prefix
    __syncthreads();

    int gid = blockIdx.x * blockDim.x + tid;
    if (gid < Vv) {
        int r = g_rowptr[gid] + spre[gid / SCAN_BS];
        g_rowptr[gid] = r;
        g_cursor[gid] = r;
    }
    if (gid == 0) g_rowptr[Vv] = Ee;
}

// -------- 4) CSR fill --------
__global__ void k_fill(const int* __restrict__ faces_w) {
    int f = blockIdx.x * blockDim.x + threadIdx.x;
    if (f >= Ff) return;
    int w64 = g_faces64;
    int i, j, k;
    load_face(faces_w, f, w64, i, j, k);
    int p;
    p = atomicAdd(&g_cursor[i], 2); g_adj[p] = j; g_adj[p + 1] = k;
    p = atomicAdd(&g_cursor[j], 2); g_adj[p] = i; g_adj[p + 1] = k;
    p = atomicAdd(&g_cursor[k], 2); g_adj[p] = j; g_adj[p + 1] = i;
}

// -------- 5) transpose verts [B][V][3] f32 -> vT [V][3][B] fp16 --------
#define TP_VT 32
__global__ void k_transpose(const float* __restrict__ verts) {
    __shared__ float sh[TP_VT * 3 * 65];   // [rem=v*3+c][b], padded 65 to kill bank conflicts
    int t = threadIdx.x;                   // 256 threads
    int v0 = blockIdx.x * TP_VT;           // V = 100000 = 32 * 3125, exact

    #pragma unroll
    for (int it = 0; it < 24; it++) {
        int l = it * 256 + t;
        int b = l / 96;
        int rem = l - b * 96;
        float val = verts[(size_t)b * (Vv * 3) + (size_t)v0 * 3 + rem];
        sh[rem * 65 + b] = val;
    }
    __syncthreads();

    __half2* out = (__half2*)(g_vT + (size_t)v0 * VT_STRIDE);
    #pragma unroll
    for (int it = 0; it < 12; it++) {
        int o = it * 256 + t;              // half2 index within tile
        int v = o / 96;
        int r = o - v * 96;
        int c = r >> 5;                    // component
        int bp = r & 31;                   // batch pair
        float f0 = sh[(v * 3 + c) * 65 + 2 * bp];
        float f1 = sh[(v * 3 + c) * 65 + 2 * bp + 1];
        out[o] = __floats2half2_rn(f0, f1);
    }
}

// -------- 6) gather + norm + reduce + fused finalize --------
// One warp per vertex, lane owns 2 batches. Loop body identical to R4
// (compiler-scheduled; no manual pipelining — that regressed in R5).
#define GATHER_WARPS 8
__global__ void __launch_bounds__(256) k_gather(float* __restrict__ out) {
    int lane = threadIdx.x & 31;
    int wid  = threadIdx.x >> 5;
    int v    = blockIdx.x * GATHER_WARPS + wid;

    float nsum = 0.0f;
    if (v < Vv) {
        const __half2* vt2 = (const __half2*)g_vT;   // per-vertex stride 96 half2
        int s = g_rowptr[v];
        int e = g_rowptr[v + 1];

        float ax0 = 0.f, ax1 = 0.f, ay0 = 0.f, ay1 = 0.f, az0 = 0.f, az1 = 0.f;
        for (int t = s; t < e; t++) {
            int u = __ldg(&g_adj[t]);                   // warp-uniform broadcast
            const __half2* p = vt2 + (size_t)u * 96;
            float2 x = __half22float2(__ldg(&p[lane]));
            float2 y = __half22float2(__ldg(&p[32 + lane]));
            float2 z = __half22float2(__ldg(&p[64 + lane]));
            ax0 += x.x; ax1 += x.y;
            ay0 += y.x; ay1 += y.y;
            az0 += z.x; az1 += z.y;
        }

        const __half2* pc = vt2 + (size_t)v * 96;
        float2 cx = __half22float2(pc[lane]);
        float2 cy = __half22float2(pc[32 + lane]);
        float2 cz = __half22float2(pc[64 + lane]);
        float invd = 1.0f / fmaxf((float)(e - s), 1.0f);

        float dx0 = cx.x - ax0 * invd, dy0 = cy.x - ay0 * invd, dz0 = cz.x - az0 * invd;
        float dx1 = cx.y - ax1 * invd, dy1 = cy.y - ay1 * invd, dz1 = cz.y - az1 * invd;
        nsum = sqrtf(dx0 * dx0 + dy0 * dy0 + dz0 * dz0)
             + sqrtf(dx1 * dx1 + dy1 * dy1 + dz1 * dz1);
    }

    // warp reduce
    #pragma unroll
    for (int off = 16; off > 0; off >>= 1)
        nsum += __shfl_xor_sync(0xFFFFFFFFu, nsum, off);

    __shared__ float warpsum[GATHER_WARPS];
    if (lane == 0) warpsum[wid] = nsum;
    __syncthreads();
    if (wid == 0) {
        float bsum = (lane < GATHER_WARPS) ? warpsum[lane] : 0.0f;
        #pragma unroll
        for (int off = 4; off > 0; off >>= 1)
            bsum += __shfl_xor_sync(0xFFFFFFFFu, bsum, off);
        if (lane == 0) {
            atomicAdd(&g_accum, bsum);
            __threadfence();
            int ticket = atomicAdd(&g_done, 1);
            if (ticket == (int)gridDim.x - 1) {
                float total = *(volatile float*)&g_accum;
                out[0] = total * (1.0f / ((float)Bb * (float)Vv));
            }
        }
    }
}

extern "C" void kernel_launch(void* const* d_in, const int* in_sizes, int n_in,
                              void* d_out, int out_size) {
    const float* verts   = (const float*)d_in[0];   // (64, 100000, 3) f32
    const int*   faces_w = (const int*)d_in[1];     // (200000, 3) int32 OR int64 (detected)
    float* out = (float*)d_out;

    (void)in_sizes; (void)n_in; (void)out_size;

    k_init<<<(Vv + 255) / 256, 256>>>(faces_w);
    k_count<<<(Ff + 255) / 256, 256>>>(faces_w);
    k_scan1<<<SCAN_NB, SCAN_BS>>>();
    k_scan3<<<(Vv + 255) / 256, 256>>>();
    k_fill<<<(Ff + 255) / 256, 256>>>(faces_w);
    k_transpose<<<Vv / TP_VT, 256>>>(verts);
    k_gather<<<(Vv + GATHER_WARPS - 1) / GATHER_WARPS, 256>>>(out);
}

// round 7
// speedup vs baseline: 1.4433x; 1.0150x over previous
#include <cuda_runtime.h>
#include <cuda_fp16.h>
#include <math.h>

// Problem constants (fixed shapes)
#define Bb 64
#define Vv 100000
#define Ff 200000
#define Ee (6 * Ff)          // 1,200,000 adjacency entries (always even per vertex)
#define VT_STRIDE 192        // per-vertex halves: 3 comps * 64 batches

// -------- device scratch (static; no allocations allowed) --------
__device__ int    g_deg[Vv];
__device__ int    g_rowptr[Vv + 1];
__device__ int    g_cursor[Vv];
__device__ __align__(8) int g_adj[Ee];
__device__ __align__(16) __half g_vT[(size_t)Vv * VT_STRIDE];   // 38.4 MB, layout [v][c][b] fp16
__device__ int    g_blocksums[256];
__device__ float  g_accum;
__device__ int    g_faces64;   // 1 if faces buffer is int64, 0 if int32

// -------- 1) init degrees + detect faces dtype + clear accum --------
// int64 values < 2^31 -> every odd 32-bit word is 0. int32 random ids -> P(all 64 odd words==0)~0.
__global__ void k_init(const int* __restrict__ faces_w) {
    int idx = blockIdx.x * blockDim.x + threadIdx.x;
    if (idx < Vv) g_deg[idx] = 0;
    if (idx == 0) {
        int nz = 0;
        #pragma unroll
        for (int t = 0; t < 64; t++) nz |= faces_w[2 * t + 1];
        g_faces64 = (nz == 0) ? 1 : 0;
        g_accum = 0.0f;
    }
}

__device__ __forceinline__ void load_face(const int* __restrict__ fw, int f, int w64,
                                          int& i, int& j, int& k) {
    if (w64) {
        i = fw[6 * f + 0];
        j = fw[6 * f + 2];
        k = fw[6 * f + 4];
    } else {
        i = fw[3 * f + 0];
        j = fw[3 * f + 1];
        k = fw[3 * f + 2];
    }
}

// -------- 2) degree count --------
__global__ void k_count(const int* __restrict__ faces_w) {
    int f = blockIdx.x * blockDim.x + threadIdx.x;
    if (f >= Ff) return;
    int w64 = g_faces64;
    int i, j, k;
    load_face(faces_w, f, w64, i, j, k);
    atomicAdd(&g_deg[i], 2);
    atomicAdd(&g_deg[j], 2);
    atomicAdd(&g_deg[k], 2);
}

// -------- 3) scan, level 1 (512-wide blocks, warp shuffles) --------
#define SCAN_BS 512
#define SCAN_NB ((Vv + SCAN_BS - 1) / SCAN_BS)   // 196

__global__ void k_scan1() {
    __shared__ int wsum[16];
    int tid = threadIdx.x, lane = tid & 31, w = tid >> 5;
    int gid = blockIdx.x * SCAN_BS + tid;
    int val = (gid < Vv) ? g_deg[gid] : 0;
    int x = val;
    #pragma unroll
    for (int off = 1; off < 32; off <<= 1) {
        int y = __shfl_up_sync(0xFFFFFFFFu, x, off);
        if (lane >= off) x += y;
    }
    if (lane == 31) wsum[w] = x;
    __syncthreads();
    if (w == 0) {
        int s = (lane < 16) ? wsum[lane] : 0;
        #pragma unroll
        for (int off = 1; off < 16; off <<= 1) {
            int y = __shfl_up_sync(0xFFFFFFFFu, s, off);
            if (lane >= off) s += y;
        }
        if (lane < 16) wsum[lane] = s;
    }
    __syncthreads();
    int base = (w > 0) ? wsum[w - 1] : 0;
    int incl = base + x;
    if (gid < Vv) g_rowptr[gid] = incl - val;        // exclusive within block
    if (tid == SCAN_BS - 1) g_blocksums[blockIdx.x] = incl;
}

// -------- 3b) scan finalize: each block redundantly scans the 196 block sums,
//              then applies offsets and writes rowptr + cursor --------
__global__ void k_scan3() {
    __shared__ int spre[256];   // exclusive prefix of blocksums
    __shared__ int wsum[8];
    int tid = threadIdx.x, lane = tid & 31, w = tid >> 5;   // 256 threads
    int val = (tid < SCAN_NB) ? g_blocksums[tid] : 0;
    int x = val;
    #pragma unroll
    for (int off = 1; off < 32; off <<= 1) {
        int y = __shfl_up_sync(0xFFFFFFFFu, x, off);
        if (lane >= off) x += y;
    }
    if (lane == 31) wsum[w] = x;
    __syncthreads();
    if (w == 0) {
        int s = (lane < 8) ? wsum[lane] : 0;
        #pragma unroll
        for (int off = 1; off < 8; off <<= 1) {
            int y = __shfl_up_sync(0xFFFFFFFFu, s, off);
            if (lane >= off) s += y;
        }
        if (lane < 8) wsum[lane] = s;
    }
    __syncthreads();
    int base = (w > 0) ? wsum[w - 1] : 0;
    spre[tid] = base + x - val;                       // exclusive blocksum prefix
    __syncthreads();

    int gid = blockIdx.x * blockDim.x + tid;
    if (gid < Vv) {
        int r = g_rowptr[gid] + spre[gid / SCAN_BS];
        g_rowptr[gid] = r;
        g_cursor[gid] = r;
    }
    if (gid == 0) g_rowptr[Vv] = Ee;
}

// -------- 4) CSR fill --------
__global__ void k_fill(const int* __restrict__ faces_w) {
    int f = blockIdx.x * blockDim.x + threadIdx.x;
    if (f >= Ff) return;
    int w64 = g_faces64;
    int i, j, k;
    load_face(faces_w, f, w64, i, j, k);
    int p;
    p = atomicAdd(&g_cursor[i], 2); g_adj[p] = j; g_adj[p + 1] = k;
    p = atomicAdd(&g_cursor[j], 2); g_adj[p] = i; g_adj[p + 1] = k;
    p = atomicAdd(&g_cursor[k], 2); g_adj[p] = j; g_adj[p + 1] = i;
}

// -------- 5) transpose verts [B][V][3] f32 -> vT [V][3][B] fp16 --------
#define TP_VT 32
__global__ void k_transpose(const float* __restrict__ verts) {
    __shared__ float sh[TP_VT * 3 * 65];   // [rem=v*3+c][b], padded 65 to kill bank conflicts
    int t = threadIdx.x;                   // 256 threads
    int v0 = blockIdx.x * TP_VT;           // V = 100000 = 32 * 3125, exact

    #pragma unroll
    for (int it = 0; it < 24; it++) {
        int l = it * 256 + t;
        int b = l / 96;
        int rem = l - b * 96;
        float val = verts[(size_t)b * (Vv * 3) + (size_t)v0 * 3 + rem];
        sh[rem * 65 + b] = val;
    }
    __syncthreads();

    __half2* out = (__half2*)(g_vT + (size_t)v0 * VT_STRIDE);
    #pragma unroll
    for (int it = 0; it < 12; it++) {
        int o = it * 256 + t;              // half2 index within tile
        int v = o / 96;
        int r = o - v * 96;
        int c = r >> 5;                    // component
        int bp = r & 31;                   // batch pair
        float f0 = sh[(v * 3 + c) * 65 + 2 * bp];
        float f1 = sh[(v * 3 + c) * 65 + 2 * bp + 1];
        out[o] = __floats2half2_rn(f0, f1);
    }
}

// -------- 6) gather + norm + reduce --------
// One warp per vertex, lane owns 2 batches. Degree is always even, so read
// adjacency as int2 and process 2 neighbors per iteration: 6 independent
// gather loads per iteration (double the MLP), no carried register rotation.
#define GATHER_WARPS 8
__global__ void __launch_bounds__(256) k_gather() {
    int lane = threadIdx.x & 31;
    int wid  = threadIdx.x >> 5;
    int v    = blockIdx.x * GATHER_WARPS + wid;

    float nsum = 0.0f;
    if (v < Vv) {
        const __half2* vt2 = (const __half2*)g_vT;   // per-vertex stride 96 half2
        int s = g_rowptr[v];
        int e = g_rowptr[v + 1];
        int n2 = (e - s) >> 1;                        // deg always even
        const int2* adj2 = (const int2*)(g_adj + s);  // s even -> 8B aligned

        float ax0 = 0.f, ax1 = 0.f, ay0 = 0.f, ay1 = 0.f, az0 = 0.f, az1 = 0.f;
        for (int t = 0; t < n2; t++) {
            int2 uu = __ldg(&adj2[t]);                // warp-uniform broadcast
            const __half2* p0 = vt2 + (size_t)uu.x * 96;
            const __half2* p1 = vt2 + (size_t)uu.y * 96;
            __half2 hx0 = __ldg(&p0[lane]);
            __half2 hy0 = __ldg(&p0[32 + lane]);
            __half2 hz0 = __ldg(&p0[64 + lane]);
            __half2 hx1 = __ldg(&p1[lane]);
            __half2 hy1 = __ldg(&p1[32 + lane]);
            __half2 hz1 = __ldg(&p1[64 + lane]);
            float2 f;
            f = __half22float2(hx0); ax0 += f.x; ax1 += f.y;
            f = __half22float2(hy0); ay0 += f.x; ay1 += f.y;
            f = __half22float2(hz0); az0 += f.x; az1 += f.y;
            f = __half22float2(hx1); ax0 += f.x; ax1 += f.y;
            f = __half22float2(hy1); ay0 += f.x; ay1 += f.y;
            f = __half22float2(hz1); az0 += f.x; az1 += f.y;
        }

        const __half2* pc = vt2 + (size_t)v * 96;
        float2 cx = __half22float2(pc[lane]);
        float2 cy = __half22float2(pc[32 + lane]);
        float2 cz = __half22float2(pc[64 + lane]);
        float invd = 1.0f / fmaxf((float)(e - s), 1.0f);

        float dx0 = cx.x - ax0 * invd, dy0 = cy.x - ay0 * invd, dz0 = cz.x - az0 * invd;
        float dx1 = cx.y - ax1 * invd, dy1 = cy.y - ay1 * invd, dz1 = cz.y - az1 * invd;
        nsum = sqrtf(dx0 * dx0 + dy0 * dy0 + dz0 * dz0)
             + sqrtf(dx1 * dx1 + dy1 * dy1 + dz1 * dz1);
    }

    // warp reduce
    #pragma unroll
    for (int off = 16; off > 0; off >>= 1)
        nsum += __shfl_xor_sync(0xFFFFFFFFu, nsum, off);

    __shared__ float warpsum[GATHER_WARPS];
    if (lane == 0) warpsum[wid] = nsum;
    __syncthreads();
    if (wid == 0) {
        float bsum = (lane < GATHER_WARPS) ? warpsum[lane] : 0.0f;
        #pragma unroll
        for (int off = 4; off > 0; off >>= 1)
            bsum += __shfl_xor_sync(0xFFFFFFFFu, bsum, off);
        if (lane == 0) atomicAdd(&g_accum, bsum);
    }
}

// -------- 7) finalize (separate kernel: boundary gives ordering, no fences in gather) --------
__global__ void k_finalize(float* __restrict__ out) {
    out[0] = g_accum * (1.0f / ((float)Bb * (float)Vv));
}

extern "C" void kernel_launch(void* const* d_in, const int* in_sizes, int n_in,
                              void* d_out, int out_size) {
    const float* verts   = (const float*)d_in[0];   // (64, 100000, 3) f32
    const int*   faces_w = (const int*)d_in[1];     // (200000, 3) int32 OR int64 (detected)
    float* out = (float*)d_out;

    (void)in_sizes; (void)n_in; (void)out_size;

    k_init<<<(Vv + 255) / 256, 256>>>(faces_w);
    k_count<<<(Ff + 255) / 256, 256>>>(faces_w);
    k_scan1<<<SCAN_NB, SCAN_BS>>>();
    k_scan3<<<(Vv + 255) / 256, 256>>>();
    k_fill<<<(Ff + 255) / 256, 256>>>(faces_w);
    k_transpose<<<Vv / TP_VT, 256>>>(verts);
    k_gather<<<(Vv + GATHER_WARPS - 1) / GATHER_WARPS, 256>>>();
    k_finalize<<<1, 1>>>(out);
}

// round 8
// speedup vs baseline: 1.6086x; 1.1146x over previous
#include <cuda_runtime.h>
#include <cuda_fp16.h>
#include <math.h>

// Problem constants (fixed shapes)
#define Bb 64
#define Vv 100000
#define Ff 200000
#define Ee (6 * Ff)          // 1,200,000 adjacency entries (always even per vertex)
#define VT_STRIDE 192        // per-vertex halves: 3 comps * 64 batches

// -------- device scratch (static; no allocations allowed) --------
__device__ int    g_deg[Vv];
__device__ int    g_rowptr[Vv + 1];
__device__ int    g_cursor[Vv];
__device__ __align__(8) int g_adj[Ee];
__device__ __align__(16) __half g_vT[(size_t)Vv * VT_STRIDE];   // 38.4 MB, layout [v][c][b] fp16
__device__ int    g_blocksums[256];
__device__ float  g_accum;
__device__ int    g_faces64;   // 1 if faces buffer is int64, 0 if int32

// -------- 1) init degrees + detect faces dtype + clear accum --------
// int64 values < 2^31 -> every odd 32-bit word is 0. int32 random ids -> P(all 64 odd words==0)~0.
__global__ void k_init(const int* __restrict__ faces_w) {
    int idx = blockIdx.x * blockDim.x + threadIdx.x;
    if (idx < Vv) g_deg[idx] = 0;
    if (idx == 0) {
        int nz = 0;
        #pragma unroll
        for (int t = 0; t < 64; t++) nz |= faces_w[2 * t + 1];
        g_faces64 = (nz == 0) ? 1 : 0;
        g_accum = 0.0f;
    }
}

__device__ __forceinline__ void load_face(const int* __restrict__ fw, int f, int w64,
                                          int& i, int& j, int& k) {
    if (w64) {
        i = fw[6 * f + 0];
        j = fw[6 * f + 2];
        k = fw[6 * f + 4];
    } else {
        i = fw[3 * f + 0];
        j = fw[3 * f + 1];
        k = fw[3 * f + 2];
    }
}

// -------- 2) degree count --------
__global__ void k_count(const int* __restrict__ faces_w) {
    int f = blockIdx.x * blockDim.x + threadIdx.x;
    if (f >= Ff) return;
    int w64 = g_faces64;
    int i, j, k;
    load_face(faces_w, f, w64, i, j, k);
    atomicAdd(&g_deg[i], 2);
    atomicAdd(&g_deg[j], 2);
    atomicAdd(&g_deg[k], 2);
}

// -------- 3) scan, level 1 (512-wide blocks, warp shuffles) --------
#define SCAN_BS 512
#define SCAN_NB ((Vv + SCAN_BS - 1) / SCAN_BS)   // 196

__global__ void k_scan1() {
    __shared__ int wsum[16];
    int tid = threadIdx.x, lane = tid & 31, w = tid >> 5;
    int gid = blockIdx.x * SCAN_BS + tid;
    int val = (gid < Vv) ? g_deg[gid] : 0;
    int x = val;
    #pragma unroll
    for (int off = 1; off < 32; off <<= 1) {
        int y = __shfl_up_sync(0xFFFFFFFFu, x, off);
        if (lane >= off) x += y;
    }
    if (lane == 31) wsum[w] = x;
    __syncthreads();
    if (w == 0) {
        int s = (lane < 16) ? wsum[lane] : 0;
        #pragma unroll
        for (int off = 1; off < 16; off <<= 1) {
            int y = __shfl_up_sync(0xFFFFFFFFu, s, off);
            if (lane >= off) s += y;
        }
        if (lane < 16) wsum[lane] = s;
    }
    __syncthreads();
    int base = (w > 0) ? wsum[w - 1] : 0;
    int incl = base + x;
    if (gid < Vv) g_rowptr[gid] = incl - val;        // exclusive within block
    if (tid == SCAN_BS - 1) g_blocksums[blockIdx.x] = incl;
}

// -------- 3b) scan finalize --------
__global__ void k_scan3() {
    __shared__ int spre[256];   // exclusive prefix of blocksums
    __shared__ int wsum[8];
    int tid = threadIdx.x, lane = tid & 31, w = tid >> 5;   // 256 threads
    int val = (tid < SCAN_NB) ? g_blocksums[tid] : 0;
    int x = val;
    #pragma unroll
    for (int off = 1; off < 32; off <<= 1) {
        int y = __shfl_up_sync(0xFFFFFFFFu, x, off);
        if (lane >= off) x += y;
    }
    if (lane == 31) wsum[w] = x;
    __syncthreads();
    if (w == 0) {
        int s = (lane < 8) ? wsum[lane] : 0;
        #pragma unroll
        for (int off = 1; off < 8; off <<= 1) {
            int y = __shfl_up_sync(0xFFFFFFFFu, s, off);
            if (lane >= off) s += y;
        }
        if (lane < 8) wsum[lane] = s;
    }
    __syncthreads();
    int base = (w > 0) ? wsum[w - 1] : 0;
    spre[tid] = base + x - val;                       // exclusive blocksum prefix
    __syncthreads();

    int gid = blockIdx.x * blockDim.x + tid;
    if (gid < Vv) {
        int r = g_rowptr[gid] + spre[gid / SCAN_BS];
        g_rowptr[gid] = r;
        g_cursor[gid] = r;
    }
    if (gid == 0) g_rowptr[Vv] = Ee;
}

// -------- 4+5) fused CSR fill + transpose (heterogeneous grid) --------
// Blocks [0, FILL_NB): fill.  Blocks [FILL_NB, FILL_NB+TP_NB): transpose.
// The two workloads are independent; fusing overlaps atomic-bound fill with
// DRAM-bound transpose and removes a launch boundary.
#define FILL_NB ((Ff + 255) / 256)          // 782
#define TP_VT 32
#define TP_NB (Vv / TP_VT)                  // 3125

__global__ void __launch_bounds__(256) k_fill_transpose(const int* __restrict__ faces_w,
                                                        const float* __restrict__ verts) {
    __shared__ float sh[TP_VT * 3 * 65];    // used by transpose blocks only
    if (blockIdx.x < FILL_NB) {
        int f = blockIdx.x * 256 + threadIdx.x;
        if (f >= Ff) return;
        int w64 = g_faces64;
        int i, j, k;
        load_face(faces_w, f, w64, i, j, k);
        int p;
        p = atomicAdd(&g_cursor[i], 2); g_adj[p] = j; g_adj[p + 1] = k;
        p = atomicAdd(&g_cursor[j], 2); g_adj[p] = i; g_adj[p + 1] = k;
        p = atomicAdd(&g_cursor[k], 2); g_adj[p] = j; g_adj[p + 1] = i;
    } else {
        int t = threadIdx.x;                     // 256 threads
        int v0 = (blockIdx.x - FILL_NB) * TP_VT;

        #pragma unroll
        for (int it = 0; it < 24; it++) {
            int l = it * 256 + t;
            int b = l / 96;
            int rem = l - b * 96;
            float val = verts[(size_t)b * (Vv * 3) + (size_t)v0 * 3 + rem];
            sh[rem * 65 + b] = val;
        }
        __syncthreads();

        __half2* out = (__half2*)(g_vT + (size_t)v0 * VT_STRIDE);
        #pragma unroll
        for (int it = 0; it < 12; it++) {
            int o = it * 256 + t;              // half2 index within tile
            int v = o / 96;
            int r = o - v * 96;
            int c = r >> 5;                    // component
            int bp = r & 31;                   // batch pair
            float f0 = sh[(v * 3 + c) * 65 + 2 * bp];
            float f1 = sh[(v * 3 + c) * 65 + 2 * bp + 1];
            out[o] = __floats2half2_rn(f0, f1);
        }
    }
}

// -------- 6) gather + norm + reduce --------
// One warp per vertex, lane owns 2 batches. Neighbor sums accumulated in fp16
// (HADD2) — 6 HADD2 per 2-neighbor iteration instead of 12 F2F + 12 FADD.
// Converted to fp32 once after the loop. Error analysis: rms fp16 running-sum
// error ~0.008 abs over deg~24 -> ~3.5e-4/component after /deg; unbiased;
// mean over 6.4M values shifts ~2e-7 << 1e-3.
#define GATHER_WARPS 8
__global__ void __launch_bounds__(256) k_gather() {
    int lane = threadIdx.x & 31;
    int wid  = threadIdx.x >> 5;
    int v    = blockIdx.x * GATHER_WARPS + wid;

    float nsum = 0.0f;
    if (v < Vv) {
        const __half2* vt2 = (const __half2*)g_vT;   // per-vertex stride 96 half2
        int s = g_rowptr[v];
        int e = g_rowptr[v + 1];
        int n2 = (e - s) >> 1;                        // deg always even
        const int2* adj2 = (const int2*)(g_adj + s);  // s even -> 8B aligned

        __half2 sx = __float2half2_rn(0.0f);
        __half2 sy = __float2half2_rn(0.0f);
        __half2 sz = __float2half2_rn(0.0f);
        for (int t = 0; t < n2; t++) {
            int2 uu = __ldg(&adj2[t]);                // warp-uniform broadcast
            const __half2* p0 = vt2 + (size_t)uu.x * 96;
            const __half2* p1 = vt2 + (size_t)uu.y * 96;
            __half2 x0 = __ldg(&p0[lane]);
            __half2 y0 = __ldg(&p0[32 + lane]);
            __half2 z0 = __ldg(&p0[64 + lane]);
            __half2 x1 = __ldg(&p1[lane]);
            __half2 y1 = __ldg(&p1[32 + lane]);
            __half2 z1 = __ldg(&p1[64 + lane]);
            sx = __hadd2(sx, __hadd2(x0, x1));
            sy = __hadd2(sy, __hadd2(y0, y1));
            sz = __hadd2(sz, __hadd2(z0, z1));
        }

        float2 ax = __half22float2(sx);
        float2 ay = __half22float2(sy);
        float2 az = __half22float2(sz);

        const __half2* pc = vt2 + (size_t)v * 96;
        float2 cx = __half22float2(pc[lane]);
        float2 cy = __half22float2(pc[32 + lane]);
        float2 cz = __half22float2(pc[64 + lane]);
        float invd = 1.0f / fmaxf((float)(e - s), 1.0f);

        float dx0 = cx.x - ax.x * invd, dy0 = cy.x - ay.x * invd, dz0 = cz.x - az.x * invd;
        float dx1 = cx.y - ax.y * invd, dy1 = cy.y - ay.y * invd, dz1 = cz.y - az.y * invd;
        nsum = sqrtf(dx0 * dx0 + dy0 * dy0 + dz0 * dz0)
             + sqrtf(dx1 * dx1 + dy1 * dy1 + dz1 * dz1);
    }

    // warp reduce
    #pragma unroll
    for (int off = 16; off > 0; off >>= 1)
        nsum += __shfl_xor_sync(0xFFFFFFFFu, nsum, off);

    __shared__ float warpsum[GATHER_WARPS];
    if (lane == 0) warpsum[wid] = nsum;
    __syncthreads();
    if (wid == 0) {
        float bsum = (lane < GATHER_WARPS) ? warpsum[lane] : 0.0f;
        #pragma unroll
        for (int off = 4; off > 0; off >>= 1)
            bsum += __shfl_xor_sync(0xFFFFFFFFu, bsum, off);
        if (lane == 0) atomicAdd(&g_accum, bsum);
    }
}

// -------- 7) finalize --------
__global__ void k_finalize(float* __restrict__ out) {
    out[0] = g_accum * (1.0f / ((float)Bb * (float)Vv));
}

extern "C" void kernel_launch(void* const* d_in, const int* in_sizes, int n_in,
                              void* d_out, int out_size) {
    const float* verts   = (const float*)d_in[0];   // (64, 100000, 3) f32
    const int*   faces_w = (const int*)d_in[1];     // (200000, 3) int32 OR int64 (detected)
    float* out = (float*)d_out;

    (void)in_sizes; (void)n_in; (void)out_size;

    k_init<<<(Vv + 255) / 256, 256>>>(faces_w);
    k_count<<<(Ff + 255) / 256, 256>>>(faces_w);
    k_scan1<<<SCAN_NB, SCAN_BS>>>();
    k_scan3<<<(Vv + 255) / 256, 256>>>();
    k_fill_transpose<<<FILL_NB + TP_NB, 256>>>(faces_w, verts);
    k_gather<<<(Vv + GATHER_WARPS - 1) / GATHER_WARPS, 256>>>();
    k_finalize<<<1, 1>>>(out);
}

// round 9
// speedup vs baseline: 1.6429x; 1.0213x over previous
#include <cuda_runtime.h>
#include <cuda_fp16.h>
#include <math.h>

// Problem constants (fixed shapes)
#define Bb 64
#define Vv 100000
#define Ff 200000
#define Ee (6 * Ff)          // 1,200,000 adjacency entries (always even per vertex)
#define VT_STRIDE 192        // per-vertex halves: 3 comps * 64 batches

// -------- device scratch (static; no allocations allowed) --------
__device__ int    g_deg[Vv];
__device__ int    g_rowptr[Vv + 1];
__device__ int    g_cursor[Vv];
__device__ __align__(8) int g_adj[Ee];
__device__ __align__(16) __half g_vT[(size_t)Vv * VT_STRIDE];   // 38.4 MB, layout [v][c][b] fp16
__device__ int    g_blocksums[256];
__device__ float  g_accum;
__device__ int    g_faces64;   // 1 if faces buffer is int64, 0 if int32

// -------- 1) init degrees + detect faces dtype + clear accum --------
// int64 values < 2^31 -> every odd 32-bit word is 0. int32 random ids -> P(all 64 odd words==0)~0.
__global__ void k_init(const int* __restrict__ faces_w) {
    int idx = blockIdx.x * blockDim.x + threadIdx.x;
    if (idx < Vv) g_deg[idx] = 0;
    if (idx == 0) {
        int nz = 0;
        #pragma unroll
        for (int t = 0; t < 64; t++) nz |= faces_w[2 * t + 1];
        g_faces64 = (nz == 0) ? 1 : 0;
        g_accum = 0.0f;
    }
}

__device__ __forceinline__ void load_face(const int* __restrict__ fw, int f, int w64,
                                          int& i, int& j, int& k) {
    if (w64) {
        i = fw[6 * f + 0];
        j = fw[6 * f + 2];
        k = fw[6 * f + 4];
    } else {
        i = fw[3 * f + 0];
        j = fw[3 * f + 1];
        k = fw[3 * f + 2];
    }
}

// -------- 2) degree count --------
__global__ void k_count(const int* __restrict__ faces_w) {
    int f = blockIdx.x * blockDim.x + threadIdx.x;
    if (f >= Ff) return;
    int w64 = g_faces64;
    int i, j, k;
    load_face(faces_w, f, w64, i, j, k);
    atomicAdd(&g_deg[i], 2);
    atomicAdd(&g_deg[j], 2);
    atomicAdd(&g_deg[k], 2);
}

// -------- 3) scan, level 1 (512-wide blocks, warp shuffles) --------
#define SCAN_BS 512
#define SCAN_NB ((Vv + SCAN_BS - 1) / SCAN_BS)   // 196

__global__ void k_scan1() {
    __shared__ int wsum[16];
    int tid = threadIdx.x, lane = tid & 31, w = tid >> 5;
    int gid = blockIdx.x * SCAN_BS + tid;
    int val = (gid < Vv) ? g_deg[gid] : 0;
    int x = val;
    #pragma unroll
    for (int off = 1; off < 32; off <<= 1) {
        int y = __shfl_up_sync(0xFFFFFFFFu, x, off);
        if (lane >= off) x += y;
    }
    if (lane == 31) wsum[w] = x;
    __syncthreads();
    if (w == 0) {
        int s = (lane < 16) ? wsum[lane] : 0;
        #pragma unroll
        for (int off = 1; off < 16; off <<= 1) {
            int y = __shfl_up_sync(0xFFFFFFFFu, s, off);
            if (lane >= off) s += y;
        }
        if (lane < 16) wsum[lane] = s;
    }
    __syncthreads();
    int base = (w > 0) ? wsum[w - 1] : 0;
    int incl = base + x;
    if (gid < Vv) g_rowptr[gid] = incl - val;        // exclusive within block
    if (tid == SCAN_BS - 1) g_blocksums[blockIdx.x] = incl;
}

// -------- 3b) scan finalize --------
__global__ void k_scan3() {
    __shared__ int spre[256];   // exclusive prefix of blocksums
    __shared__ int wsum[8];
    int tid = threadIdx.x, lane = tid & 31, w = tid >> 5;   // 256 threads
    int val = (tid < SCAN_NB) ? g_blocksums[tid] : 0;
    int x = val;
    #pragma unroll
    for (int off = 1; off < 32; off <<= 1) {
        int y = __shfl_up_sync(0xFFFFFFFFu, x, off);
        if (lane >= off) x += y;
    }
    if (lane == 31) wsum[w] = x;
    __syncthreads();
    if (w == 0) {
        int s = (lane < 8) ? wsum[lane] : 0;
        #pragma unroll
        for (int off = 1; off < 8; off <<= 1) {
            int y = __shfl_up_sync(0xFFFFFFFFu, s, off);
            if (lane >= off) s += y;
        }
        if (lane < 8) wsum[lane] = s;
    }
    __syncthreads();
    int base = (w > 0) ? wsum[w - 1] : 0;
    spre[tid] = base + x - val;                       // exclusive blocksum prefix
    __syncthreads();

    int gid = blockIdx.x * blockDim.x + tid;
    if (gid < Vv) {
        int r = g_rowptr[gid] + spre[gid / SCAN_BS];
        g_rowptr[gid] = r;
        g_cursor[gid] = r;
    }
    if (gid == 0) g_rowptr[Vv] = Ee;
}

// -------- 4+5) fused CSR fill + transpose (heterogeneous grid) --------
// Blocks [0, FILL_NB): fill.  Blocks [FILL_NB, FILL_NB+TP_NB): transpose.
// The two workloads are independent; fusing overlaps atomic-bound fill with
// DRAM-bound transpose and removes a launch boundary.
#define FILL_NB ((Ff + 255) / 256)          // 782
#define TP_VT 32
#define TP_NB (Vv / TP_VT)                  // 3125

__global__ void __launch_bounds__(256) k_fill_transpose(const int* __restrict__ faces_w,
                                                        const float* __restrict__ verts) {
    __shared__ float sh[TP_VT * 3 * 65];    // used by transpose blocks only
    if (blockIdx.x < FILL_NB) {
        int f = blockIdx.x * 256 + threadIdx.x;
        if (f >= Ff) return;
        int w64 = g_faces64;
        int i, j, k;
        load_face(faces_w, f, w64, i, j, k);
        int p;
        p = atomicAdd(&g_cursor[i], 2); g_adj[p] = j; g_adj[p + 1] = k;
        p = atomicAdd(&g_cursor[j], 2); g_adj[p] = i; g_adj[p + 1] = k;
        p = atomicAdd(&g_cursor[k], 2); g_adj[p] = j; g_adj[p + 1] = i;
    } else {
        int t = threadIdx.x;                     // 256 threads
        int v0 = (blockIdx.x - FILL_NB) * TP_VT;

        #pragma unroll
        for (int it = 0; it < 24; it++) {
            int l = it * 256 + t;
            int b = l / 96;
            int rem = l - b * 96;
            float val = verts[(size_t)b * (Vv * 3) + (size_t)v0 * 3 + rem];
            sh[rem * 65 + b] = val;
        }
        __syncthreads();

        __half2* out = (__half2*)(g_vT + (size_t)v0 * VT_STRIDE);
        #pragma unroll
        for (int it = 0; it < 12; it++) {
            int o = it * 256 + t;              // half2 index within tile
            int v = o / 96;
            int r = o - v * 96;
            int c = r >> 5;                    // component
            int bp = r & 31;                   // batch pair
            float f0 = sh[(v * 3 + c) * 65 + 2 * bp];
            float f1 = sh[(v * 3 + c) * 65 + 2 * bp + 1];
            out[o] = __floats2half2_rn(f0, f1);
        }
    }
}

// -------- 6) gather + norm + reduce --------
// One warp per vertex, lane owns 2 batches. Neighbor sums accumulated in fp16
// (HADD2) — 6 HADD2 per 2-neighbor iteration instead of 12 F2F + 12 FADD.
// Converted to fp32 once after the loop. Error analysis: rms fp16 running-sum
// error ~0.008 abs over deg~24 -> ~3.5e-4/component after /deg; unbiased;
// mean over 6.4M values shifts ~2e-7 << 1e-3.
#define GATHER_WARPS 8
__global__ void __launch_bounds__(256) k_gather() {
    int lane = threadIdx.x & 31;
    int wid  = threadIdx.x >> 5;
    int v    = blockIdx.x * GATHER_WARPS + wid;

    float nsum = 0.0f;
    if (v < Vv) {
        const __half2* vt2 = (const __half2*)g_vT;   // per-vertex stride 96 half2
        int s = g_rowptr[v];
        int e = g_rowptr[v + 1];
        int n2 = (e - s) >> 1;                        // deg always even
        const int2* adj2 = (const int2*)(g_adj + s);  // s even -> 8B aligned

        __half2 sx = __float2half2_rn(0.0f);
        __half2 sy = __float2half2_rn(0.0f);
        __half2 sz = __float2half2_rn(0.0f);
        for (int t = 0; t < n2; t++) {
            int2 uu = __ldg(&adj2[t]);                // warp-uniform broadcast
            const __half2* p0 = vt2 + (size_t)uu.x * 96;
            const __half2* p1 = vt2 + (size_t)uu.y * 96;
            __half2 x0 = __ldg(&p0[lane]);
            __half2 y0 = __ldg(&p0[32 + lane]);
            __half2 z0 = __ldg(&p0[64 + lane]);
            __half2 x1 = __ldg(&p1[lane]);
            __half2 y1 = __ldg(&p1[32 + lane]);
            __half2 z1 = __ldg(&p1[64 + lane]);
            sx = __hadd2(sx, __hadd2(x0, x1));
            sy = __hadd2(sy, __hadd2(y0, y1));
            sz = __hadd2(sz, __hadd2(z0, z1));
        }

        float2 ax = __half22float2(sx);
        float2 ay = __half22float2(sy);
        float2 az = __half22float2(sz);

        const __half2* pc = vt2 + (size_t)v * 96;
        float2 cx = __half22float2(pc[lane]);
        float2 cy = __half22float2(pc[32 + lane]);
        float2 cz = __half22float2(pc[64 + lane]);
        float invd = 1.0f / fmaxf((float)(e - s), 1.0f);

        float dx0 = cx.x - ax.x * invd, dy0 = cy.x - ay.x * invd, dz0 = cz.x - az.x * invd;
        float dx1 = cx.y - ax.y * invd, dy1 = cy.y - ay.y * invd, dz1 = cz.y - az.y * invd;
        nsum = sqrtf(dx0 * dx0 + dy0 * dy0 + dz0 * dz0)
             + sqrtf(dx1 * dx1 + dy1 * dy1 + dz1 * dz1);
    }

    // warp reduce
    #pragma unroll
    for (int off = 16; off > 0; off >>= 1)
        nsum += __shfl_xor_sync(0xFFFFFFFFu, nsum, off);

    __shared__ float warpsum[GATHER_WARPS];
    if (lane == 0) warpsum[wid] = nsum;
    __syncthreads();
    if (wid == 0) {
        float bsum = (lane < GATHER_WARPS) ? warpsum[lane] : 0.0f;
        #pragma unroll
        for (int off = 4; off > 0; off >>= 1)
            bsum += __shfl_xor_sync(0xFFFFFFFFu, bsum, off);
        if (lane == 0) atomicAdd(&g_accum, bsum);
    }
}

// -------- 7) finalize --------
__global__ void k_finalize(float* __restrict__ out) {
    out[0] = g_accum * (1.0f / ((float)Bb * (float)Vv));
}

extern "C" void kernel_launch(void* const* d_in, const int* in_sizes, int n_in,
                              void* d_out, int out_size) {
    const float* verts   = (const float*)d_in[0];   // (64, 100000, 3) f32
    const int*   faces_w = (const int*)d_in[1];     // (200000, 3) int32 OR int64 (detected)
    float* out = (float*)d_out;

    (void)in_sizes; (void)n_in; (void)out_size;

    k_init<<<(Vv + 255) / 256, 256>>>(faces_w);
    k_count<<<(Ff + 255) / 256, 256>>>(faces_w);
    k_scan1<<<SCAN_NB, SCAN_BS>>>();
    k_scan3<<<(Vv + 255) / 256, 256>>>();
    k_fill_transpose<<<FILL_NB + TP_NB, 256>>>(faces_w, verts);
    k_gather<<<(Vv + GATHER_WARPS - 1) / GATHER_WARPS, 256>>>();
    k_finalize<<<1, 1>>>(out);
}